// round 16
// baseline (speedup 1.0000x reference)
#include <cuda_runtime.h>
#include <cuda_fp16.h>
#include <stdint.h>

#define BATCH   32
#define HDIM    4096
#define IDIM    2048
#define NCOLS   4096
#define GSZ     128

#define KSPLIT  16       // both GEMMs
#define MTILE   64       // weight columns per block
#define KCHUNK  64       // K per pipeline stage
#define THREADS 128
#define STAGES  4        // smem ring stages (up to 3 chunks in flight)

// ---------------- scratch ------------------------------------------------
__device__ __align__(16) __half g_xh[BATCH * HDIM];      // x fp16 [b][k]
__device__ __align__(16) __half g_acth[BATCH * IDIM];    // act fp16 [b][i]
__device__ float g_hpart[KSPLIT][NCOLS * BATCH];         // gemm1 partials [s][n][b]
__device__ float g_opart[KSPLIT][NCOLS * BATCH];         // gemm2 partials [s][n][b]

// ---------------- helpers -------------------------------------------------
__device__ __forceinline__ uint32_t smem_u32(const void* p) {
    uint32_t a;
    asm("{ .reg .u64 t; cvta.to.shared.u64 t, %1; cvt.u32.u64 %0, t; }"
        : "=r"(a) : "l"(p));
    return a;
}
#define CP16(dst, src) \
    asm volatile("cp.async.cg.shared.global [%0], [%1], 16;" \
                 :: "r"(dst), "l"(src) : "memory")
#define CP_COMMIT() asm volatile("cp.async.commit_group;" ::: "memory")
#define CP_WAIT2()  asm volatile("cp.async.wait_group 2;"  ::: "memory")

__device__ __forceinline__ void ldsm_x4(uint32_t& r0, uint32_t& r1,
                                        uint32_t& r2, uint32_t& r3, uint32_t addr) {
    asm volatile("ldmatrix.sync.aligned.m8n8.x4.shared.b16 {%0,%1,%2,%3}, [%4];"
                 : "=r"(r0), "=r"(r1), "=r"(r2), "=r"(r3) : "r"(addr));
}
__device__ __forceinline__ void mma_16816(float* c, const uint32_t* a, const uint32_t* b) {
    asm volatile(
        "mma.sync.aligned.m16n8k16.row.col.f32.f16.f16.f32 "
        "{%0,%1,%2,%3}, {%4,%5,%6,%7}, {%8,%9}, {%0,%1,%2,%3};"
        : "+f"(c[0]), "+f"(c[1]), "+f"(c[2]), "+f"(c[3])
        : "r"(a[0]), "r"(a[1]), "r"(a[2]), "r"(a[3]), "r"(b[0]), "r"(b[1]));
}

// Dequant byte sel of packed word w -> RAW fp16x2 (values = fp4 * 2^-14,
// incl. the 2^-15 subnormal for +-0.5; HMMA is subnormal-exact, verified R15).
// Scale applied later in the f32 epilogue.
__device__ __forceinline__ uint32_t dqb(uint32_t w, uint32_t sel) {
    uint32_t t;
    asm("prmt.b32 %0, %1, %1, %2;" : "=r"(t) : "r"(w), "r"(sel));
    return ((t << 9) & 0x00000E00u) | ((t << 4) & 0x00008000u)
         | ((t << 5) & 0x0E000000u) | (t & 0x80000000u);
}

// ---------------- prep: x f32 -> fp16 ------------------------------------
__global__ void __launch_bounds__(512) prep_x_kernel(const float* __restrict__ x) {
    int idx = blockIdx.x * 512 + threadIdx.x;
    g_xh[idx] = __float2half_rn(x[idx]);   // exact: x was fp16 originally
}

// ---------------- cp.async HMMA dequant-GEMM (deferred f32 scaling) ------
// partial[n][b] += sum_k dequant(W[k][n]) * act[b][k]
// NSG accumulator sets (one per GSZ=128 scale group in this block's kspan);
// scale*2^14 applied once in the f32 epilogue.
template <int KDIM, bool PHASE1>
__global__ void __launch_bounds__(THREADS) gemm_mma_kernel(
    const int*   __restrict__ packed,   // [KDIM/8][NCOLS]
    const float* __restrict__ scales)   // [KDIM/GSZ][NCOLS]
{
    constexpr int KSPAN = KDIM / KSPLIT;          // 256 (gemm1) / 128 (gemm2)
    constexpr int NCH   = KSPAN / KCHUNK;         // 4 / 2
    constexpr int NSG   = KSPAN / GSZ;            // 2 / 1 scale groups

    __shared__ __align__(16) uint32_t Ap [STAGES][8 * MTILE];       // packed W, 2 KB/stage
    __shared__ __align__(16) __half   Bsh[STAGES][BATCH * KCHUNK];  // 4 KB/stage

    const int tid  = threadIdx.x;
    const int wid  = tid >> 5;
    const int lane = tid & 31;

    const int n_base  = blockIdx.x * MTILE;
    const int k_begin = blockIdx.y * KSPAN;

    // ---- cp.async source/dst mapping ----
    const int r  = tid >> 4;
    const int n4 = (tid & 15) * 4;
    const uint32_t* asrc0 = (const uint32_t*)packed
                          + (size_t)((k_begin >> 3) + r) * NCOLS + n_base + n4;
    const int brow = tid >> 2;
    const int bcx2 = (tid & 3) * 2;
    const __half* __restrict__ Bsrc = PHASE1 ? g_xh : g_acth;
    const __half* bsrc0 = Bsrc + (size_t)brow * KDIM + k_begin + bcx2 * 8;
    uint32_t adst[STAGES], bdst[STAGES][2];
    #pragma unroll
    for (int s = 0; s < STAGES; ++s) {
        adst[s] = smem_u32(&Ap[s][r * MTILE + n4]);
        bdst[s][0] = smem_u32(&Bsh[s][brow * KCHUNK + ((bcx2 ^ (brow & 7)) * 8)]);
        bdst[s][1] = smem_u32(&Bsh[s][brow * KCHUNK + (((bcx2 + 1) ^ (brow & 7)) * 8)]);
    }

    auto issue = [&](int c, int st) {
        CP16(adst[st], asrc0 + (size_t)c * 8 * NCOLS);
        CP16(bdst[st][0], bsrc0 + (size_t)c * KCHUNK);
        CP16(bdst[st][1], bsrc0 + (size_t)c * KCHUNK + 8);
    };

    // ---- prologue: up to 3 chunks in flight (uniform group count) ----
    issue(0, 0);              CP_COMMIT();
    if (NCH > 1) issue(1, 1); CP_COMMIT();
    if (NCH > 2) issue(2, 2); CP_COMMIT();

    // ---- MMA lane addressing ----
    float acc[NSG][4][4] = {};                 // [scale group][n8 tile][frag]
    const int sub = lane >> 3, l7 = lane & 7;
    const int mrow = wid * 16;                 // warp's m16 slice of MTILE=64
    const int n0l  = mrow + (lane >> 2);       // A fragment rows (tile-local n)
    const int n1l  = n0l + 8;
    const uint32_t sel = (uint32_t)(lane & 3) * 0x1111u;
    const int bn0 = l7 + (sub >> 1) * 8;       // B ldmatrix row base
    const int bcx_off = sub & 1;

    #pragma unroll
    for (int c = 0; c < NCH; ++c) {
        CP_WAIT2();           // chunk c's group (and all before) complete
        __syncthreads();      // visible to all; prior compute on reused stage done
        if (c + 3 < NCH) issue(c + 3, (c + 3) & (STAGES - 1));
        CP_COMMIT();          // commit every iter (uniform group count)

        const int st = c & (STAGES - 1);
        const uint32_t* ap = &Ap[st][0];
        const uint32_t Bb = smem_u32(&Bsh[st][0]);
        float (*ac)[4] = acc[(NSG > 1) ? (c >> 1) : 0];   // GSZ = 2*KCHUNK

        #pragma unroll
        for (int ks = 0; ks < 4; ++ks) {
            // A fragment: raw dequant (no scale) from packed smem words
            uint32_t a[4];
            {
                const uint32_t w00 = ap[(2 * ks)     * MTILE + n0l];
                const uint32_t w10 = ap[(2 * ks)     * MTILE + n1l];
                const uint32_t w01 = ap[(2 * ks + 1) * MTILE + n0l];
                const uint32_t w11 = ap[(2 * ks + 1) * MTILE + n1l];
                a[0] = dqb(w00, sel);
                a[1] = dqb(w10, sel);
                a[2] = dqb(w01, sel);
                a[3] = dqb(w11, sel);
            }
            // B fragments
            uint32_t b0[4], b1[4];
            const int bcxs = ks * 2 + bcx_off;
            {
                const int n = bn0;
                ldsm_x4(b0[0], b0[1], b0[2], b0[3],
                        Bb + (uint32_t)(n * (KCHUNK * 2))
                           + (uint32_t)((bcxs ^ (n & 7)) << 4));
            }
            {
                const int n = bn0 + 16;
                ldsm_x4(b1[0], b1[1], b1[2], b1[3],
                        Bb + (uint32_t)(n * (KCHUNK * 2))
                           + (uint32_t)((bcxs ^ (n & 7)) << 4));
            }
            mma_16816(ac[0], a, &b0[0]);
            mma_16816(ac[1], a, &b0[2]);
            mma_16816(ac[2], a, &b1[0]);
            mma_16816(ac[3], a, &b1[2]);
        }
    }

    // ---- epilogue: apply scales in f32, store partials [n][b] ----
    // fragment rows: acc[*][t][0..1] -> row n0l, acc[*][t][2..3] -> row n1l
    const int sg0 = k_begin / GSZ;
    float s0[NSG], s1[NSG];
    #pragma unroll
    for (int g = 0; g < NSG; ++g) {
        s0[g] = scales[(size_t)(sg0 + g) * NCOLS + n_base + n0l] * 16384.0f;
        s1[g] = scales[(size_t)(sg0 + g) * NCOLS + n_base + n1l] * 16384.0f;
    }

    float* partp = (PHASE1 ? &g_hpart[0][0] : &g_opart[0][0])
                  + (size_t)blockIdx.y * (NCOLS * BATCH);
    const int gq = lane >> 2, tq = lane & 3;
    const int nrow0 = n_base + mrow + gq;
    #pragma unroll
    for (int t = 0; t < 4; ++t) {
        const int bcol = t * 8 + tq * 2;
        float o0 = 0.f, o1 = 0.f, o2 = 0.f, o3 = 0.f;
        #pragma unroll
        for (int g = 0; g < NSG; ++g) {
            o0 += acc[g][t][0] * s0[g];
            o1 += acc[g][t][1] * s0[g];
            o2 += acc[g][t][2] * s1[g];
            o3 += acc[g][t][3] * s1[g];
        }
        *(float2*)&partp[(size_t)nrow0 * BATCH + bcol]       = make_float2(o0, o1);
        *(float2*)&partp[(size_t)(nrow0 + 8) * BATCH + bcol] = make_float2(o2, o3);
    }
}

// ---------------- SwiGLU: reduce gemm1 partials -> act fp16 [b][i] -------
__global__ void __launch_bounds__(256) swiglu_kernel() {
    __shared__ float s_act[8][33];
    const int i0 = blockIdx.x * 8;
    const int b  = threadIdx.x & 31;
    const int il = threadIdx.x >> 5;          // 0..7
    {
        const size_t ng = (size_t)(i0 + il) * BATCH + b;
        float hg = 0.f, hu = 0.f;
        #pragma unroll
        for (int s = 0; s < KSPLIT; ++s) {
            hg += g_hpart[s][ng];
            hu += g_hpart[s][ng + (size_t)IDIM * BATCH];
        }
        const float sig = 1.0f / (1.0f + __expf(-hg));
        s_act[il][b] = hg * sig * hu;
    }
    __syncthreads();
    const int bb = threadIdx.x >> 3;          // 0..31
    const int pp = threadIdx.x & 3;           // 0..3 half2 pairs
    if ((threadIdx.x & 4) == 0) {
        __half2 h = __float22half2_rn(make_float2(s_act[pp * 2][bb], s_act[pp * 2 + 1][bb]));
        *(__half2*)&g_acth[(size_t)bb * IDIM + i0 + pp * 2] = h;
    }
}

// ---------------- reduce gemm2 partials [n][b] -> out [b][n] f32 ---------
__global__ void __launch_bounds__(256) reduce_out_kernel(float* __restrict__ out) {
    __shared__ float s_o[16][33];
    const int h0 = blockIdx.x * 16;
    const int b  = threadIdx.x & 31;
    const int hl = threadIdx.x >> 5;          // 0..7
    {
        const size_t ng0 = (size_t)(h0 + hl) * BATCH + b;
        const size_t ng1 = (size_t)(h0 + hl + 8) * BATCH + b;
        float s0 = 0.f, s1 = 0.f;
        #pragma unroll
        for (int sp = 0; sp < KSPLIT; ++sp) {
            s0 += g_opart[sp][ng0];
            s1 += g_opart[sp][ng1];
        }
        s_o[hl][b]     = s0;
        s_o[hl + 8][b] = s1;
    }
    __syncthreads();
    const int bb = threadIdx.x >> 3;          // 0..31
    const int h2 = threadIdx.x & 7;           // 0..7
    out[(size_t)bb * NCOLS + h0 + h2] =
        __half2float(__float2half_rn(s_o[h2][bb]));
    out[(size_t)bb * NCOLS + h0 + h2 + 8] =
        __half2float(__float2half_rn(s_o[h2 + 8][bb]));
}

// ---------------- launch --------------------------------------------------
extern "C" void kernel_launch(void* const* d_in, const int* in_sizes, int n_in,
                              void* d_out, int out_size) {
    const float* x   = (const float*)d_in[0];
    const int*   gup = (const int*)  d_in[1];
    const float* gus = (const float*)d_in[2];
    const int*   dwn = (const int*)  d_in[3];
    const float* dws = (const float*)d_in[4];
    float* out = (float*)d_out;

    prep_x_kernel<<<(BATCH * HDIM) / 512, 512>>>(x);

    gemm_mma_kernel<HDIM, true><<<dim3(NCOLS / MTILE, KSPLIT), THREADS>>>(gup, gus);

    swiglu_kernel<<<IDIM / 8, 256>>>();

    gemm_mma_kernel<IDIM, false><<<dim3(NCOLS / MTILE, KSPLIT), THREADS>>>(dwn, dws);

    reduce_out_kernel<<<NCOLS / 16, 256>>>(out);
}

// round 17
// speedup vs baseline: 1.0835x; 1.0835x over previous
#include <cuda_runtime.h>
#include <cuda_fp16.h>
#include <stdint.h>

#define BATCH   32
#define HDIM    4096
#define IDIM    2048
#define NCOLS   4096
#define GSZ     128

#define KSPLIT  16       // both GEMMs
#define MTILE   64       // weight columns per block
#define KCHUNK  64       // K per chunk
#define THREADS 128

// ---------------- scratch ------------------------------------------------
__device__ __align__(16) __half g_xh[BATCH * HDIM];      // x fp16 [b][k]
__device__ __align__(16) __half g_acth[BATCH * IDIM];    // act fp16 [b][i]
__device__ float g_hpart[KSPLIT][NCOLS * BATCH];         // gemm1 partials [s][n][b]
__device__ float g_opart[KSPLIT][NCOLS * BATCH];         // gemm2 partials [s][n][b]

// ---------------- helpers -------------------------------------------------
__device__ __forceinline__ uint32_t smem_u32(const void* p) {
    uint32_t a;
    asm("{ .reg .u64 t; cvta.to.shared.u64 t, %1; cvt.u32.u64 %0, t; }"
        : "=r"(a) : "l"(p));
    return a;
}
#define CP16(dst, src) \
    asm volatile("cp.async.cg.shared.global [%0], [%1], 16;" \
                 :: "r"(dst), "l"(src) : "memory")
#define CP_COMMIT() asm volatile("cp.async.commit_group;" ::: "memory")
template <int N>
__device__ __forceinline__ void cp_wait() {
    asm volatile("cp.async.wait_group %0;" :: "n"(N) : "memory");
}
#define GDC_WAIT()   asm volatile("griddepcontrol.wait;" ::: "memory")
#define GDC_LAUNCH() asm volatile("griddepcontrol.launch_dependents;" ::: "memory")

__device__ __forceinline__ void ldsm_x4(uint32_t& r0, uint32_t& r1,
                                        uint32_t& r2, uint32_t& r3, uint32_t addr) {
    asm volatile("ldmatrix.sync.aligned.m8n8.x4.shared.b16 {%0,%1,%2,%3}, [%4];"
                 : "=r"(r0), "=r"(r1), "=r"(r2), "=r"(r3) : "r"(addr));
}
__device__ __forceinline__ void mma_16816(float* c, const uint32_t* a, const uint32_t* b) {
    asm volatile(
        "mma.sync.aligned.m16n8k16.row.col.f32.f16.f16.f32 "
        "{%0,%1,%2,%3}, {%4,%5,%6,%7}, {%8,%9}, {%0,%1,%2,%3};"
        : "+f"(c[0]), "+f"(c[1]), "+f"(c[2]), "+f"(c[3])
        : "r"(a[0]), "r"(a[1]), "r"(a[2]), "r"(a[3]), "r"(b[0]), "r"(b[1]));
}

// Dequant byte sel of packed word w -> RAW fp16x2 (values = fp4 * 2^-14,
// incl. the 2^-15 subnormal for +-0.5; HMMA is subnormal-exact, verified R15).
__device__ __forceinline__ uint32_t dqb(uint32_t w, uint32_t sel) {
    uint32_t t;
    asm("prmt.b32 %0, %1, %1, %2;" : "=r"(t) : "r"(w), "r"(sel));
    return ((t << 9) & 0x00000E00u) | ((t << 4) & 0x00008000u)
         | ((t << 5) & 0x0E000000u) | (t & 0x80000000u);
}

// ---------------- prep: x f32 -> fp16 ------------------------------------
__global__ void __launch_bounds__(512) prep_x_kernel(const float* __restrict__ x) {
    int idx = blockIdx.x * 512 + threadIdx.x;
    g_xh[idx] = __float2half_rn(x[idx]);   // exact: x was fp16 originally
    GDC_LAUNCH();
}

// ---------------- cp.async HMMA dequant-GEMM -----------------------------
// A (weights) issued in full BEFORE griddepcontrol.wait (no producer dep);
// B (activations) via LDG->STS double buffer after the wait.
template <int KDIM, bool PHASE1>
__global__ void __launch_bounds__(THREADS) gemm_mma_kernel(
    const int*   __restrict__ packed,   // [KDIM/8][NCOLS]
    const float* __restrict__ scales)   // [KDIM/GSZ][NCOLS]
{
    constexpr int KSPAN = KDIM / KSPLIT;          // 256 (gemm1) / 128 (gemm2)
    constexpr int NCH   = KSPAN / KCHUNK;         // 4 / 2
    constexpr int NSG   = KSPAN / GSZ;            // 2 / 1 scale groups

    __shared__ __align__(16) uint32_t Ap [4][8 * MTILE];        // all chunks resident
    __shared__ __align__(16) __half   Bsh[2][BATCH * KCHUNK];   // double buffer

    const int tid  = threadIdx.x;
    const int wid  = tid >> 5;
    const int lane = tid & 31;

    const int n_base  = blockIdx.x * MTILE;
    const int k_begin = blockIdx.y * KSPAN;

    // ---- A: issue ALL chunks now (input data, no dependency) ----
    const int r  = tid >> 4;
    const int n4 = (tid & 15) * 4;
    const uint32_t* asrc0 = (const uint32_t*)packed
                          + (size_t)((k_begin >> 3) + r) * NCOLS + n_base + n4;
    #pragma unroll
    for (int c = 0; c < NCH; ++c) {
        CP16(smem_u32(&Ap[c][r * MTILE + n4]), asrc0 + (size_t)c * 8 * NCOLS);
        CP_COMMIT();
    }

    // ---- wait for producer (prep_x / swiglu) before touching B ----
    GDC_WAIT();

    // ---- B mapping: LDG -> STS, 2 x 16B per thread per chunk ----
    const int brow = tid >> 2;
    const int bcx2 = (tid & 3) * 2;
    const __half* __restrict__ Bsrc = PHASE1 ? g_xh : g_acth;
    const __half* bsrc0 = Bsrc + (size_t)brow * KDIM + k_begin + bcx2 * 8;
    __half* bsp[2][2];
    #pragma unroll
    for (int bf = 0; bf < 2; ++bf) {
        bsp[bf][0] = &Bsh[bf][brow * KCHUNK + ((bcx2 ^ (brow & 7)) * 8)];
        bsp[bf][1] = &Bsh[bf][brow * KCHUNK + (((bcx2 + 1) ^ (brow & 7)) * 8)];
    }

    uint4 xv0[2], xv1[2];
    xv0[0] = *(const uint4*)(bsrc0);
    xv0[1] = *(const uint4*)(bsrc0 + 8);
    if (NCH > 1) {
        xv1[0] = *(const uint4*)(bsrc0 + KCHUNK);
        xv1[1] = *(const uint4*)(bsrc0 + KCHUNK + 8);
    }

    // ---- MMA lane addressing ----
    float acc[NSG][4][4] = {};                 // [scale group][n8 tile][frag]
    const int sub = lane >> 3, l7 = lane & 7;
    const int mrow = wid * 16;
    const int n0l  = mrow + (lane >> 2);
    const int n1l  = n0l + 8;
    const uint32_t sel = (uint32_t)(lane & 3) * 0x1111u;
    const int bn0 = l7 + (sub >> 1) * 8;
    const int bcx_off = sub & 1;

    #pragma unroll
    for (int c = 0; c < NCH; ++c) {
        // wait for A chunk c (groups drain in order; allow NCH-1-c pending)
        if      (c == 0) cp_wait<(NCH >= 1) ? NCH - 1 : 0>();
        else if (c == 1) cp_wait<(NCH >= 2) ? NCH - 2 : 0>();
        else if (c == 2) cp_wait<1>();
        else             cp_wait<0>();

        // store B chunk c (buffer c&1; iter c-1's sync proved compute(c-2) done)
        const int buf = c & 1;
        *(uint4*)bsp[buf][0] = (c & 1) ? xv1[0] : xv0[0];
        *(uint4*)bsp[buf][1] = (c & 1) ? xv1[1] : xv0[1];
        __syncthreads();

        // prefetch B chunk c+2 into freed slot
        if (c + 2 < NCH) {
            uint4* dst = (c & 1) ? xv1 : xv0;
            dst[0] = *(const uint4*)(bsrc0 + (size_t)(c + 2) * KCHUNK);
            dst[1] = *(const uint4*)(bsrc0 + (size_t)(c + 2) * KCHUNK + 8);
        }

        const uint32_t* ap = &Ap[c][0];
        const uint32_t Bb = smem_u32(&Bsh[buf][0]);
        float (*ac)[4] = acc[(NSG > 1) ? (c >> 1) : 0];

        #pragma unroll
        for (int ks = 0; ks < 4; ++ks) {
            uint32_t a[4];
            {
                const uint32_t w00 = ap[(2 * ks)     * MTILE + n0l];
                const uint32_t w10 = ap[(2 * ks)     * MTILE + n1l];
                const uint32_t w01 = ap[(2 * ks + 1) * MTILE + n0l];
                const uint32_t w11 = ap[(2 * ks + 1) * MTILE + n1l];
                a[0] = dqb(w00, sel);
                a[1] = dqb(w10, sel);
                a[2] = dqb(w01, sel);
                a[3] = dqb(w11, sel);
            }
            uint32_t b0[4], b1[4];
            const int bcxs = ks * 2 + bcx_off;
            {
                const int n = bn0;
                ldsm_x4(b0[0], b0[1], b0[2], b0[3],
                        Bb + (uint32_t)(n * (KCHUNK * 2))
                           + (uint32_t)((bcxs ^ (n & 7)) << 4));
            }
            {
                const int n = bn0 + 16;
                ldsm_x4(b1[0], b1[1], b1[2], b1[3],
                        Bb + (uint32_t)(n * (KCHUNK * 2))
                           + (uint32_t)((bcxs ^ (n & 7)) << 4));
            }
            mma_16816(ac[0], a, &b0[0]);
            mma_16816(ac[1], a, &b0[2]);
            mma_16816(ac[2], a, &b1[0]);
            mma_16816(ac[3], a, &b1[2]);
        }

        // barrier at end of iter: everyone done with buffer before iter c+2 writes it
        if (c + 1 < NCH) __syncthreads();
    }

    // ---- epilogue: apply scales in f32, store partials [n][b] ----
    const int sg0 = k_begin / GSZ;
    float s0[NSG], s1[NSG];
    #pragma unroll
    for (int g = 0; g < NSG; ++g) {
        s0[g] = scales[(size_t)(sg0 + g) * NCOLS + n_base + n0l] * 16384.0f;
        s1[g] = scales[(size_t)(sg0 + g) * NCOLS + n_base + n1l] * 16384.0f;
    }

    float* partp = (PHASE1 ? &g_hpart[0][0] : &g_opart[0][0])
                  + (size_t)blockIdx.y * (NCOLS * BATCH);
    const int gq = lane >> 2, tq = lane & 3;
    const int nrow0 = n_base + mrow + gq;
    #pragma unroll
    for (int t = 0; t < 4; ++t) {
        const int bcol = t * 8 + tq * 2;
        float o0 = 0.f, o1 = 0.f, o2 = 0.f, o3 = 0.f;
        #pragma unroll
        for (int g = 0; g < NSG; ++g) {
            o0 += acc[g][t][0] * s0[g];
            o1 += acc[g][t][1] * s0[g];
            o2 += acc[g][t][2] * s1[g];
            o3 += acc[g][t][3] * s1[g];
        }
        *(float2*)&partp[(size_t)nrow0 * BATCH + bcol]       = make_float2(o0, o1);
        *(float2*)&partp[(size_t)(nrow0 + 8) * BATCH + bcol] = make_float2(o2, o3);
    }
    GDC_LAUNCH();
}

// ---------------- SwiGLU: reduce gemm1 partials -> act fp16 [b][i] -------
__global__ void __launch_bounds__(256) swiglu_kernel() {
    GDC_WAIT();
    __shared__ float s_act[8][33];
    const int i0 = blockIdx.x * 8;
    const int b  = threadIdx.x & 31;
    const int il = threadIdx.x >> 5;
    {
        const size_t ng = (size_t)(i0 + il) * BATCH + b;
        float hg = 0.f, hu = 0.f;
        #pragma unroll
        for (int s = 0; s < KSPLIT; ++s) {
            hg += g_hpart[s][ng];
            hu += g_hpart[s][ng + (size_t)IDIM * BATCH];
        }
        const float sig = 1.0f / (1.0f + __expf(-hg));
        s_act[il][b] = hg * sig * hu;
    }
    __syncthreads();
    const int bb = threadIdx.x >> 3;
    const int pp = threadIdx.x & 3;
    if ((threadIdx.x & 4) == 0) {
        __half2 h = __float22half2_rn(make_float2(s_act[pp * 2][bb], s_act[pp * 2 + 1][bb]));
        *(__half2*)&g_acth[(size_t)bb * IDIM + i0 + pp * 2] = h;
    }
    GDC_LAUNCH();
}

// ---------------- reduce gemm2 partials [n][b] -> out [b][n] f32 ---------
__global__ void __launch_bounds__(256) reduce_out_kernel(float* __restrict__ out) {
    GDC_WAIT();
    __shared__ float s_o[16][33];
    const int h0 = blockIdx.x * 16;
    const int b  = threadIdx.x & 31;
    const int hl = threadIdx.x >> 5;
    {
        const size_t ng0 = (size_t)(h0 + hl) * BATCH + b;
        const size_t ng1 = (size_t)(h0 + hl + 8) * BATCH + b;
        float s0 = 0.f, s1 = 0.f;
        #pragma unroll
        for (int sp = 0; sp < KSPLIT; ++sp) {
            s0 += g_opart[sp][ng0];
            s1 += g_opart[sp][ng1];
        }
        s_o[hl][b]     = s0;
        s_o[hl + 8][b] = s1;
    }
    __syncthreads();
    const int bb = threadIdx.x >> 3;
    const int h2 = threadIdx.x & 7;
    out[(size_t)bb * NCOLS + h0 + h2] =
        __half2float(__float2half_rn(s_o[h2][bb]));
    out[(size_t)bb * NCOLS + h0 + h2 + 8] =
        __half2float(__float2half_rn(s_o[h2 + 8][bb]));
}

// ---------------- launch (PDL on dependents) ------------------------------
static void launch_pdl(const void* func, dim3 grid, dim3 block, void** args) {
    cudaLaunchConfig_t cfg = {};
    cfg.gridDim = grid;
    cfg.blockDim = block;
    cfg.dynamicSmemBytes = 0;
    cfg.stream = 0;
    cudaLaunchAttribute attr[1];
    attr[0].id = cudaLaunchAttributeProgrammaticStreamSerialization;
    attr[0].val.programmaticStreamSerializationAllowed = 1;
    cfg.attrs = attr;
    cfg.numAttrs = 1;
    cudaLaunchKernelExC(&cfg, func, args);
}

extern "C" void kernel_launch(void* const* d_in, const int* in_sizes, int n_in,
                              void* d_out, int out_size) {
    const float* x   = (const float*)d_in[0];
    const int*   gup = (const int*)  d_in[1];
    const float* gus = (const float*)d_in[2];
    const int*   dwn = (const int*)  d_in[3];
    const float* dws = (const float*)d_in[4];
    float* out = (float*)d_out;

    prep_x_kernel<<<(BATCH * HDIM) / 512, 512>>>(x);

    {
        void* args[] = { (void*)&gup, (void*)&gus };
        launch_pdl((const void*)&gemm_mma_kernel<HDIM, true>,
                   dim3(NCOLS / MTILE, KSPLIT), dim3(THREADS), args);
    }
    {
        void* args[] = {};
        launch_pdl((const void*)&swiglu_kernel, dim3(IDIM / 8), dim3(256), args);
    }
    {
        void* args[] = { (void*)&dwn, (void*)&dws };
        launch_pdl((const void*)&gemm_mma_kernel<IDIM, false>,
                   dim3(NCOLS / MTILE, KSPLIT), dim3(THREADS), args);
    }
    {
        void* args[] = { (void*)&out };
        launch_pdl((const void*)&reduce_out_kernel, dim3(NCOLS / 16), dim3(256), args);
    }
}